// round 3
// baseline (speedup 1.0000x reference)
#include <cuda_runtime.h>
#include <cuda_bf16.h>
#include <math.h>

// Problem shape (fixed by dataset)
#define BB 2
#define SS 2048
#define EE 2048
#define HH 16
#define DD 128
#define MM (BB*SS)        // 4096 rows
#define HD (HH*DD)        // 2048

// -------------------- scratch (device globals; no cudaMalloc allowed) ----------
__device__ float g_Q[MM * HD];     // 33.5 MB  Q projection (then RoPE'd in-place)
__device__ float g_K[MM * DD];     // 2 MB
__device__ float g_V[MM * DD];     // 2 MB
__device__ float g_A[MM * HD];     // 33.5 MB  attention output [B*S, H*D]

// ============================================================================
// Tiled SGEMM with bias epilogue, double-buffered smem + register prefetch.
// A[M,K] row-major, B[K,N] row-major, C[M,N].  256 threads.
// ============================================================================
template<int BM, int BN, int BK, int TM, int TN>
__global__ __launch_bounds__(256)
void sgemm_bias(const float* __restrict__ A, const float* __restrict__ B,
                const float* __restrict__ bias, float* __restrict__ C,
                int M, int N, int K)
{
    __shared__ float As[2][BK][BM];
    __shared__ float Bs[2][BK][BN];

    const int tid  = threadIdx.x;
    const int col0 = blockIdx.x * BN;
    const int row0 = blockIdx.y * BM;

    constexpr int A_VECS = BM * BK / 4;   // float4 loads for the A tile
    constexpr int B_VECS = BK * BN / 4;
    const int a_r = tid / (BK / 4);
    const int a_c = (tid % (BK / 4)) * 4;
    const int b_r = tid / (BN / 4);
    const int b_c = (tid % (BN / 4)) * 4;
    const bool a_act = (A_VECS == 256) || (tid < A_VECS);
    const bool b_act = (B_VECS == 256) || (tid < B_VECS);

    const int ty = tid / (BN / TN);
    const int tx = tid % (BN / TN);

    float acc[TM][TN];
#pragma unroll
    for (int i = 0; i < TM; ++i)
#pragma unroll
        for (int j = 0; j < TN; ++j) acc[i][j] = 0.f;

    // ---- prologue: load tile 0 into buffer 0 ----
    if (a_act) {
        float4 v = *(const float4*)(A + (size_t)(row0 + a_r) * K + a_c);
        As[0][a_c + 0][a_r] = v.x;
        As[0][a_c + 1][a_r] = v.y;
        As[0][a_c + 2][a_r] = v.z;
        As[0][a_c + 3][a_r] = v.w;
    }
    if (b_act) {
        *(float4*)(&Bs[0][b_r][b_c]) =
            *(const float4*)(B + (size_t)b_r * N + col0 + b_c);
    }
    __syncthreads();

    int cur = 0;
    for (int k0 = 0; k0 < K; k0 += BK) {
        const bool has_next = (k0 + BK) < K;
        float4 av, bv;
        if (has_next) {                       // prefetch next tile into registers
            if (a_act)
                av = *(const float4*)(A + (size_t)(row0 + a_r) * K + k0 + BK + a_c);
            if (b_act)
                bv = *(const float4*)(B + (size_t)(k0 + BK + b_r) * N + col0 + b_c);
        }

        // ---- compute from buffer `cur` ----
#pragma unroll
        for (int kk = 0; kk < BK; ++kk) {
            float ar[TM], br[TN];
#pragma unroll
            for (int v = 0; v < TM / 4; ++v) {
                float4 t = *(const float4*)(&As[cur][kk][ty * TM + 4 * v]);
                ar[4*v+0] = t.x; ar[4*v+1] = t.y; ar[4*v+2] = t.z; ar[4*v+3] = t.w;
            }
#pragma unroll
            for (int v = 0; v < TN / 4; ++v) {
                float4 t = *(const float4*)(&Bs[cur][kk][tx * TN + 4 * v]);
                br[4*v+0] = t.x; br[4*v+1] = t.y; br[4*v+2] = t.z; br[4*v+3] = t.w;
            }
#pragma unroll
            for (int i = 0; i < TM; ++i)
#pragma unroll
                for (int j = 0; j < TN; ++j)
                    acc[i][j] += ar[i] * br[j];
        }

        // ---- store prefetched tile into the other buffer ----
        if (has_next) {
            const int nxt = cur ^ 1;
            if (a_act) {
                As[nxt][a_c + 0][a_r] = av.x;
                As[nxt][a_c + 1][a_r] = av.y;
                As[nxt][a_c + 2][a_r] = av.z;
                As[nxt][a_c + 3][a_r] = av.w;
            }
            if (b_act)
                *(float4*)(&Bs[nxt][b_r][b_c]) = bv;
        }
        __syncthreads();
        cur ^= 1;
    }

    // epilogue: C = acc + bias
#pragma unroll
    for (int i = 0; i < TM; ++i) {
        const int row = row0 + ty * TM + i;
#pragma unroll
        for (int v = 0; v < TN / 4; ++v) {
            const int col = col0 + tx * TN + 4 * v;
            float4 bvv = *(const float4*)(bias + col);
            float4 o;
            o.x = acc[i][4*v+0] + bvv.x;
            o.y = acc[i][4*v+1] + bvv.y;
            o.z = acc[i][4*v+2] + bvv.z;
            o.w = acc[i][4*v+3] + bvv.w;
            *(float4*)(C + (size_t)row * N + col) = o;
        }
    }
}

// ============================================================================
// Rotate-half RoPE, in place.  X: [rows, H*128] row-major, pos = row % S.
// ============================================================================
__global__ void rope_kernel(float* __restrict__ X, int S, int H, int rows)
{
    int idx = blockIdx.x * blockDim.x + threadIdx.x;
    int total = rows * H * (DD / 2);
    if (idx >= total) return;

    int i   = idx & 63;                 // pair index 0..63
    int h   = (idx >> 6) % H;
    int row = idx / (64 * H);
    int s   = row % S;

    float inv_freq = (float)pow(10000.0, -(double)(2 * i) / 128.0);
    float ang = (float)s * inv_freq;    // f32 product, same as reference
    float c, sn;
    sincosf(ang, &sn, &c);

    float* p = X + (size_t)row * (H * DD) + h * DD + i;
    float q1 = p[0], q2 = p[64];
    p[0]  = q1 * c - q2 * sn;
    p[64] = q1 * sn + q2 * c;
}

// ============================================================================
// Flash attention (causal, MQA).  One block = 128 q rows of one (b,h).
// Q: [B*S, H*128], K/V: [B*S, 128], O: [B*S, H*128].
// 256 threads.  QK^T: 8x4 micro-tile.  PV: 8x8 micro-tile.
// Dyn smem: Qs[128][132] | KVs[64][132] (K then V reuse) | Ss[128][65] | row state.
// ============================================================================
#define FL_QR 128
#define FL_KR 64
#define FL_PAD 132
#define FL_SPAD 65
#define FLASH_SMEM ((FL_QR*FL_PAD + FL_KR*FL_PAD + FL_QR*FL_SPAD + 3*FL_QR) * 4)

__global__ __launch_bounds__(256, 1)
void flash_attn_kernel(const float* __restrict__ Q, const float* __restrict__ K,
                       const float* __restrict__ V, float* __restrict__ O,
                       int S, int H)
{
    extern __shared__ float sm[];
    float* Qs       = sm;                        // [128][132]
    float* KVs      = Qs + FL_QR * FL_PAD;       // [64][132]
    float* Ss       = KVs + FL_KR * FL_PAD;      // [128][65]
    float* row_m    = Ss + FL_QR * FL_SPAD;      // [128]
    float* row_l    = row_m + FL_QR;             // [128]
    float* row_alph = row_l + FL_QR;             // [128]

    const int qt  = blockIdx.x;
    const int h   = blockIdx.y;
    const int b   = blockIdx.z;
    const int tid = threadIdx.x;
    const int tx  = tid & 15;     // 0..15
    const int ty  = tid >> 4;     // 0..15
    const int qbase = qt * FL_QR;
    const float scale = 0.08838834764831845f;    // 1/sqrt(128)

    // ---- load Q tile (128 x 128) ----
    const float* Qg = Q + (size_t)(b * S + qbase) * (H * DD) + h * DD;
    for (int l = tid; l < FL_QR * 32; l += 256) {
        int r = l >> 5, cv = (l & 31) * 4;
        *(float4*)(Qs + r * FL_PAD + cv) =
            *(const float4*)(Qg + (size_t)r * (H * DD) + cv);
    }
    if (tid < FL_QR) { row_m[tid] = -INFINITY; row_l[tid] = 0.f; }

    // O accumulator: rows ty+16i (i<8), d-cols tx+16jo (jo<8)
    float o[8][8];
#pragma unroll
    for (int i = 0; i < 8; ++i)
#pragma unroll
        for (int j = 0; j < 8; ++j) o[i][j] = 0.f;

    __syncthreads();

    const float* Kg = K + (size_t)(b * S) * DD;
    const float* Vg = V + (size_t)(b * S) * DD;

    const int n_kt = (qbase + FL_QR) / FL_KR;    // causal: need k < qbase+128
    for (int kt = 0; kt < n_kt; ++kt) {
        const int kbase = kt * FL_KR;

        // ---- load K tile (64 x 128) into KVs ----
        for (int l = tid; l < FL_KR * 32; l += 256) {
            int r = l >> 5, cv = (l & 31) * 4;
            *(float4*)(KVs + r * FL_PAD + cv) =
                *(const float4*)(Kg + (size_t)(kbase + r) * DD + cv);
        }
        __syncthreads();

        // ---- S = Q K^T : 8x4 micro-tile (rows ty+16i, cols tx+16j) ----
        float acc[8][4];
#pragma unroll
        for (int i = 0; i < 8; ++i)
#pragma unroll
            for (int j = 0; j < 4; ++j) acc[i][j] = 0.f;

#pragma unroll 4
        for (int kk = 0; kk < DD; kk += 2) {
            float2 ar[8], br[4];
#pragma unroll
            for (int i = 0; i < 8; ++i)
                ar[i] = *(const float2*)(Qs + (ty + 16 * i) * FL_PAD + kk);
#pragma unroll
            for (int j = 0; j < 4; ++j)
                br[j] = *(const float2*)(KVs + (tx + 16 * j) * FL_PAD + kk);
#pragma unroll
            for (int i = 0; i < 8; ++i)
#pragma unroll
                for (int j = 0; j < 4; ++j)
                    acc[i][j] += ar[i].x * br[j].x + ar[i].y * br[j].y;
        }

        // ---- mask + scale, stage into Ss ----
#pragma unroll
        for (int i = 0; i < 8; ++i) {
            int rg = qbase + ty + 16 * i;
#pragma unroll
            for (int j = 0; j < 4; ++j) {
                int cg = kbase + tx + 16 * j;
                float s = acc[i][j] * scale;
                if (cg > rg) s = -INFINITY;
                Ss[(ty + 16 * i) * FL_SPAD + tx + 16 * j] = s;
            }
        }
        __syncthreads();

        // ---- online softmax (2 threads per row) + concurrent V tile load ----
        {
            int row = tid >> 1, q2 = tid & 1;
            float mloc = -INFINITY;
#pragma unroll
            for (int t = 0; t < 32; ++t)
                mloc = fmaxf(mloc, Ss[row * FL_SPAD + q2 + 2 * t]);
            mloc = fmaxf(mloc, __shfl_xor_sync(0xffffffffu, mloc, 1));
            float mold = row_m[row];
            float mnew = fmaxf(mold, mloc);
            float suml = 0.f;
#pragma unroll
            for (int t = 0; t < 32; ++t) {
                int c = q2 + 2 * t;
                float p = expf(Ss[row * FL_SPAD + c] - mnew);
                Ss[row * FL_SPAD + c] = p;
                suml += p;
            }
            suml += __shfl_xor_sync(0xffffffffu, suml, 1);
            if (q2 == 0) {
                float alpha = expf(mold - mnew);     // 0 when mold = -inf
                row_alph[row] = alpha;
                row_l[row] = row_l[row] * alpha + suml;
                row_m[row] = mnew;
            }
        }
        // V load into KVs (all K reads finished before the Ss barrier above)
        for (int l = tid; l < FL_KR * 32; l += 256) {
            int r = l >> 5, cv = (l & 31) * 4;
            *(float4*)(KVs + r * FL_PAD + cv) =
                *(const float4*)(Vg + (size_t)(kbase + r) * DD + cv);
        }
        __syncthreads();

        // ---- O = O*alpha + P V : 8x8 micro-tile ----
        float al[8];
#pragma unroll
        for (int i = 0; i < 8; ++i) al[i] = row_alph[ty + 16 * i];
#pragma unroll
        for (int i = 0; i < 8; ++i)
#pragma unroll
            for (int jo = 0; jo < 8; ++jo) o[i][jo] *= al[i];

#pragma unroll 2
        for (int j = 0; j < FL_KR; ++j) {
            float pv[8], vv[8];
#pragma unroll
            for (int i = 0; i < 8; ++i)
                pv[i] = Ss[(ty + 16 * i) * FL_SPAD + j];
#pragma unroll
            for (int jo = 0; jo < 8; ++jo)
                vv[jo] = KVs[j * FL_PAD + tx + 16 * jo];
#pragma unroll
            for (int i = 0; i < 8; ++i)
#pragma unroll
                for (int jo = 0; jo < 8; ++jo)
                    o[i][jo] += pv[i] * vv[jo];
        }
        __syncthreads();   // before next iter overwrites KVs / Ss
    }

    // ---- normalize and write out ----
    float* Og = O + (size_t)(b * S + qbase) * (H * DD) + h * DD;
#pragma unroll
    for (int i = 0; i < 8; ++i) {
        float inv_l = 1.f / row_l[ty + 16 * i];
#pragma unroll
        for (int jo = 0; jo < 8; ++jo)
            Og[(size_t)(ty + 16 * i) * (H * DD) + tx + 16 * jo] = o[i][jo] * inv_l;
    }
}

// ============================================================================
// kernel_launch
// ============================================================================
extern "C" void kernel_launch(void* const* d_in, const int* in_sizes, int n_in,
                              void* d_out, int out_size)
{
    (void)in_sizes; (void)n_in; (void)out_size;
    const float* x   = (const float*)d_in[0];
    const float* W_q = (const float*)d_in[1];
    const float* b_q = (const float*)d_in[2];
    const float* W_k = (const float*)d_in[3];
    const float* b_k = (const float*)d_in[4];
    const float* W_v = (const float*)d_in[5];
    const float* b_v = (const float*)d_in[6];
    const float* W_o = (const float*)d_in[7];
    const float* b_o = (const float*)d_in[8];
    float* out = (float*)d_out;

    float *Qb, *Kb, *Vb, *Ab;
    cudaGetSymbolAddress((void**)&Qb, g_Q);
    cudaGetSymbolAddress((void**)&Kb, g_K);
    cudaGetSymbolAddress((void**)&Vb, g_V);
    cudaGetSymbolAddress((void**)&Ab, g_A);

    // Q projection: [4096,2048] = x @ W_q + b_q
    dim3 gBig(HD / 128, MM / 128);            // (16, 32)
    sgemm_bias<128,128,8,8,8><<<gBig, 256>>>(x, W_q, b_q, Qb, MM, HD, EE);

    // K / V projections: [4096,128]
    dim3 gNar(DD / 64, MM / 64);              // (2, 64)
    sgemm_bias<64,64,8,4,4><<<gNar, 256>>>(x, W_k, b_k, Kb, MM, DD, EE);
    sgemm_bias<64,64,8,4,4><<<gNar, 256>>>(x, W_v, b_v, Vb, MM, DD, EE);

    // RoPE in place
    {
        int totQ = MM * HH * (DD / 2);
        rope_kernel<<<(totQ + 255) / 256, 256>>>(Qb, SS, HH, MM);
        int totK = MM * 1 * (DD / 2);
        rope_kernel<<<(totK + 255) / 256, 256>>>(Kb, SS, 1, MM);
    }

    // flash attention
    cudaFuncSetAttribute(flash_attn_kernel,
                         cudaFuncAttributeMaxDynamicSharedMemorySize, FLASH_SMEM);
    flash_attn_kernel<<<dim3(SS / FL_QR, HH, BB), 256, FLASH_SMEM>>>(Qb, Kb, Vb, Ab, SS, HH);

    // output projection: out = A @ W_o + b_o   [4096,2048]
    dim3 gOut(EE / 128, MM / 128);            // (16, 32)
    sgemm_bias<128,128,8,8,8><<<gOut, 256>>>(Ab, W_o, b_o, out, MM, EE, HD);
}

// round 4
// speedup vs baseline: 1.2001x; 1.2001x over previous
#include <cuda_runtime.h>
#include <cuda_bf16.h>
#include <math.h>

// Problem shape (fixed by dataset)
#define BB 2
#define SS 2048
#define EE 2048
#define HH 16
#define DD 128
#define MM (BB*SS)        // 4096 rows
#define HD (HH*DD)        // 2048

// -------------------- scratch (device globals; no cudaMalloc allowed) ----------
__device__ float g_Q[MM * HD];     // 33.5 MB  Q projection (then RoPE'd in-place)
__device__ float g_K[MM * DD];     // 2 MB
__device__ float g_V[MM * DD];     // 2 MB
__device__ float g_A[MM * HD];     // 33.5 MB  attention output [B*S, H*D]

// ============================================================================
// Tiled SGEMM with bias epilogue, double-buffered smem + register prefetch.
// A[M,K] row-major, B[K,N] row-major, C[M,N].  256 threads.
// ============================================================================
template<int BM, int BN, int BK, int TM, int TN>
__global__ __launch_bounds__(256)
void sgemm_bias(const float* __restrict__ A, const float* __restrict__ B,
                const float* __restrict__ bias, float* __restrict__ C,
                int M, int N, int K)
{
    __shared__ float As[2][BK][BM];
    __shared__ float Bs[2][BK][BN];

    const int tid  = threadIdx.x;
    const int col0 = blockIdx.x * BN;
    const int row0 = blockIdx.y * BM;

    constexpr int A_VECS = BM * BK / 4;   // float4 loads for the A tile
    constexpr int B_VECS = BK * BN / 4;
    const int a_r = tid / (BK / 4);
    const int a_c = (tid % (BK / 4)) * 4;
    const int b_r = tid / (BN / 4);
    const int b_c = (tid % (BN / 4)) * 4;
    const bool a_act = (A_VECS == 256) || (tid < A_VECS);
    const bool b_act = (B_VECS == 256) || (tid < B_VECS);

    const int ty = tid / (BN / TN);
    const int tx = tid % (BN / TN);

    float acc[TM][TN];
#pragma unroll
    for (int i = 0; i < TM; ++i)
#pragma unroll
        for (int j = 0; j < TN; ++j) acc[i][j] = 0.f;

    // ---- prologue: load tile 0 into buffer 0 ----
    if (a_act) {
        float4 v = *(const float4*)(A + (size_t)(row0 + a_r) * K + a_c);
        As[0][a_c + 0][a_r] = v.x;
        As[0][a_c + 1][a_r] = v.y;
        As[0][a_c + 2][a_r] = v.z;
        As[0][a_c + 3][a_r] = v.w;
    }
    if (b_act) {
        *(float4*)(&Bs[0][b_r][b_c]) =
            *(const float4*)(B + (size_t)b_r * N + col0 + b_c);
    }
    __syncthreads();

    int cur = 0;
    for (int k0 = 0; k0 < K; k0 += BK) {
        const bool has_next = (k0 + BK) < K;
        float4 av, bv;
        if (has_next) {                       // prefetch next tile into registers
            if (a_act)
                av = *(const float4*)(A + (size_t)(row0 + a_r) * K + k0 + BK + a_c);
            if (b_act)
                bv = *(const float4*)(B + (size_t)(k0 + BK + b_r) * N + col0 + b_c);
        }

        // ---- compute from buffer `cur` ----
#pragma unroll
        for (int kk = 0; kk < BK; ++kk) {
            float ar[TM], br[TN];
#pragma unroll
            for (int v = 0; v < TM / 4; ++v) {
                float4 t = *(const float4*)(&As[cur][kk][ty * TM + 4 * v]);
                ar[4*v+0] = t.x; ar[4*v+1] = t.y; ar[4*v+2] = t.z; ar[4*v+3] = t.w;
            }
#pragma unroll
            for (int v = 0; v < TN / 4; ++v) {
                float4 t = *(const float4*)(&Bs[cur][kk][tx * TN + 4 * v]);
                br[4*v+0] = t.x; br[4*v+1] = t.y; br[4*v+2] = t.z; br[4*v+3] = t.w;
            }
#pragma unroll
            for (int i = 0; i < TM; ++i)
#pragma unroll
                for (int j = 0; j < TN; ++j)
                    acc[i][j] += ar[i] * br[j];
        }

        // ---- store prefetched tile into the other buffer ----
        if (has_next) {
            const int nxt = cur ^ 1;
            if (a_act) {
                As[nxt][a_c + 0][a_r] = av.x;
                As[nxt][a_c + 1][a_r] = av.y;
                As[nxt][a_c + 2][a_r] = av.z;
                As[nxt][a_c + 3][a_r] = av.w;
            }
            if (b_act)
                *(float4*)(&Bs[nxt][b_r][b_c]) = bv;
        }
        __syncthreads();
        cur ^= 1;
    }

    // epilogue: C = acc + bias
#pragma unroll
    for (int i = 0; i < TM; ++i) {
        const int row = row0 + ty * TM + i;
#pragma unroll
        for (int v = 0; v < TN / 4; ++v) {
            const int col = col0 + tx * TN + 4 * v;
            float4 bvv = *(const float4*)(bias + col);
            float4 o;
            o.x = acc[i][4*v+0] + bvv.x;
            o.y = acc[i][4*v+1] + bvv.y;
            o.z = acc[i][4*v+2] + bvv.z;
            o.w = acc[i][4*v+3] + bvv.w;
            *(float4*)(C + (size_t)row * N + col) = o;
        }
    }
}

// ============================================================================
// Rotate-half RoPE, in place.  X: [rows, H*128] row-major, pos = row % S.
// inv_freq computed in fp32 via exp2f (was fp64 pow: 638us -> memory bound).
// ============================================================================
__global__ void rope_kernel(float* __restrict__ X, int S, int H, int rows)
{
    int idx = blockIdx.x * blockDim.x + threadIdx.x;
    int total = rows * H * (DD / 2);
    if (idx >= total) return;

    int i   = idx & 63;                 // pair index 0..63
    int h   = (idx >> 6) % H;
    int row = idx / (64 * H);
    int s   = row % S;

    // inv_freq = 10000^(-2i/128) = 2^( -(i/64) * log2(10000) )
    // (i/64 exact in fp32; exp2f ~2ulp -> matches reference f32 to ~3e-7 rel)
    const float LOG2_THETA = 13.28771237954945f;   // log2(10000)
    float t = (float)i * (1.0f / 64.0f);
    float inv_freq = exp2f(-t * LOG2_THETA);
    float ang = (float)s * inv_freq;    // f32 product, same as reference
    float c, sn;
    sincosf(ang, &sn, &c);

    float* p = X + (size_t)row * (H * DD) + h * DD + i;
    float q1 = p[0], q2 = p[64];
    p[0]  = q1 * c - q2 * sn;
    p[64] = q1 * sn + q2 * c;
}

// ============================================================================
// Flash attention (causal, MQA).  One block = 128 q rows of one (b,h).
// Q: [B*S, H*128], K/V: [B*S, 128], O: [B*S, H*128].
// 256 threads.  QK^T: 8x4 micro-tile.  PV: 8x8 micro-tile.
// Dyn smem: Qs[128][132] | KVs[64][132] (K then V reuse) | Ss[128][65] | row state.
// ============================================================================
#define FL_QR 128
#define FL_KR 64
#define FL_PAD 132
#define FL_SPAD 65
#define FLASH_SMEM ((FL_QR*FL_PAD + FL_KR*FL_PAD + FL_QR*FL_SPAD + 3*FL_QR) * 4)

__global__ __launch_bounds__(256, 1)
void flash_attn_kernel(const float* __restrict__ Q, const float* __restrict__ K,
                       const float* __restrict__ V, float* __restrict__ O,
                       int S, int H)
{
    extern __shared__ float sm[];
    float* Qs       = sm;                        // [128][132]
    float* KVs      = Qs + FL_QR * FL_PAD;       // [64][132]
    float* Ss       = KVs + FL_KR * FL_PAD;      // [128][65]
    float* row_m    = Ss + FL_QR * FL_SPAD;      // [128]
    float* row_l    = row_m + FL_QR;             // [128]
    float* row_alph = row_l + FL_QR;             // [128]

    const int qt  = blockIdx.x;
    const int h   = blockIdx.y;
    const int b   = blockIdx.z;
    const int tid = threadIdx.x;
    const int tx  = tid & 15;     // 0..15
    const int ty  = tid >> 4;     // 0..15
    const int qbase = qt * FL_QR;
    const float scale = 0.08838834764831845f;    // 1/sqrt(128)

    // ---- load Q tile (128 x 128) ----
    const float* Qg = Q + (size_t)(b * S + qbase) * (H * DD) + h * DD;
    for (int l = tid; l < FL_QR * 32; l += 256) {
        int r = l >> 5, cv = (l & 31) * 4;
        *(float4*)(Qs + r * FL_PAD + cv) =
            *(const float4*)(Qg + (size_t)r * (H * DD) + cv);
    }
    if (tid < FL_QR) { row_m[tid] = -INFINITY; row_l[tid] = 0.f; }

    // O accumulator: rows ty+16i (i<8), d-cols tx+16jo (jo<8)
    float o[8][8];
#pragma unroll
    for (int i = 0; i < 8; ++i)
#pragma unroll
        for (int j = 0; j < 8; ++j) o[i][j] = 0.f;

    __syncthreads();

    const float* Kg = K + (size_t)(b * S) * DD;
    const float* Vg = V + (size_t)(b * S) * DD;

    const int n_kt = (qbase + FL_QR) / FL_KR;    // causal: need k < qbase+128
    for (int kt = 0; kt < n_kt; ++kt) {
        const int kbase = kt * FL_KR;

        // ---- load K tile (64 x 128) into KVs ----
        for (int l = tid; l < FL_KR * 32; l += 256) {
            int r = l >> 5, cv = (l & 31) * 4;
            *(float4*)(KVs + r * FL_PAD + cv) =
                *(const float4*)(Kg + (size_t)(kbase + r) * DD + cv);
        }
        __syncthreads();

        // ---- S = Q K^T : 8x4 micro-tile (rows ty+16i, cols tx+16j) ----
        float acc[8][4];
#pragma unroll
        for (int i = 0; i < 8; ++i)
#pragma unroll
            for (int j = 0; j < 4; ++j) acc[i][j] = 0.f;

#pragma unroll 4
        for (int kk = 0; kk < DD; kk += 2) {
            float2 ar[8], br[4];
#pragma unroll
            for (int i = 0; i < 8; ++i)
                ar[i] = *(const float2*)(Qs + (ty + 16 * i) * FL_PAD + kk);
#pragma unroll
            for (int j = 0; j < 4; ++j)
                br[j] = *(const float2*)(KVs + (tx + 16 * j) * FL_PAD + kk);
#pragma unroll
            for (int i = 0; i < 8; ++i)
#pragma unroll
                for (int j = 0; j < 4; ++j)
                    acc[i][j] += ar[i].x * br[j].x + ar[i].y * br[j].y;
        }

        // ---- mask + scale, stage into Ss ----
#pragma unroll
        for (int i = 0; i < 8; ++i) {
            int rg = qbase + ty + 16 * i;
#pragma unroll
            for (int j = 0; j < 4; ++j) {
                int cg = kbase + tx + 16 * j;
                float s = acc[i][j] * scale;
                if (cg > rg) s = -INFINITY;
                Ss[(ty + 16 * i) * FL_SPAD + tx + 16 * j] = s;
            }
        }
        __syncthreads();

        // ---- online softmax (2 threads per row) + concurrent V tile load ----
        {
            int row = tid >> 1, q2 = tid & 1;
            float mloc = -INFINITY;
#pragma unroll
            for (int t = 0; t < 32; ++t)
                mloc = fmaxf(mloc, Ss[row * FL_SPAD + q2 + 2 * t]);
            mloc = fmaxf(mloc, __shfl_xor_sync(0xffffffffu, mloc, 1));
            float mold = row_m[row];
            float mnew = fmaxf(mold, mloc);
            float suml = 0.f;
#pragma unroll
            for (int t = 0; t < 32; ++t) {
                int c = q2 + 2 * t;
                float p = expf(Ss[row * FL_SPAD + c] - mnew);
                Ss[row * FL_SPAD + c] = p;
                suml += p;
            }
            suml += __shfl_xor_sync(0xffffffffu, suml, 1);
            if (q2 == 0) {
                float alpha = expf(mold - mnew);     // 0 when mold = -inf
                row_alph[row] = alpha;
                row_l[row] = row_l[row] * alpha + suml;
                row_m[row] = mnew;
            }
        }
        // V load into KVs (all K reads finished before the Ss barrier above)
        for (int l = tid; l < FL_KR * 32; l += 256) {
            int r = l >> 5, cv = (l & 31) * 4;
            *(float4*)(KVs + r * FL_PAD + cv) =
                *(const float4*)(Vg + (size_t)(kbase + r) * DD + cv);
        }
        __syncthreads();

        // ---- O = O*alpha + P V : 8x8 micro-tile ----
        float al[8];
#pragma unroll
        for (int i = 0; i < 8; ++i) al[i] = row_alph[ty + 16 * i];
#pragma unroll
        for (int i = 0; i < 8; ++i)
#pragma unroll
            for (int jo = 0; jo < 8; ++jo) o[i][jo] *= al[i];

#pragma unroll 2
        for (int j = 0; j < FL_KR; ++j) {
            float pv[8], vv[8];
#pragma unroll
            for (int i = 0; i < 8; ++i)
                pv[i] = Ss[(ty + 16 * i) * FL_SPAD + j];
#pragma unroll
            for (int jo = 0; jo < 8; ++jo)
                vv[jo] = KVs[j * FL_PAD + tx + 16 * jo];
#pragma unroll
            for (int i = 0; i < 8; ++i)
#pragma unroll
                for (int jo = 0; jo < 8; ++jo)
                    o[i][jo] += pv[i] * vv[jo];
        }
        __syncthreads();   // before next iter overwrites KVs / Ss
    }

    // ---- normalize and write out ----
    float* Og = O + (size_t)(b * S + qbase) * (H * DD) + h * DD;
#pragma unroll
    for (int i = 0; i < 8; ++i) {
        float inv_l = 1.f / row_l[ty + 16 * i];
#pragma unroll
        for (int jo = 0; jo < 8; ++jo)
            Og[(size_t)(ty + 16 * i) * (H * DD) + tx + 16 * jo] = o[i][jo] * inv_l;
    }
}

// ============================================================================
// kernel_launch
// ============================================================================
extern "C" void kernel_launch(void* const* d_in, const int* in_sizes, int n_in,
                              void* d_out, int out_size)
{
    (void)in_sizes; (void)n_in; (void)out_size;
    const float* x   = (const float*)d_in[0];
    const float* W_q = (const float*)d_in[1];
    const float* b_q = (const float*)d_in[2];
    const float* W_k = (const float*)d_in[3];
    const float* b_k = (const float*)d_in[4];
    const float* W_v = (const float*)d_in[5];
    const float* b_v = (const float*)d_in[6];
    const float* W_o = (const float*)d_in[7];
    const float* b_o = (const float*)d_in[8];
    float* out = (float*)d_out;

    float *Qb, *Kb, *Vb, *Ab;
    cudaGetSymbolAddress((void**)&Qb, g_Q);
    cudaGetSymbolAddress((void**)&Kb, g_K);
    cudaGetSymbolAddress((void**)&Vb, g_V);
    cudaGetSymbolAddress((void**)&Ab, g_A);

    // Q projection: [4096,2048] = x @ W_q + b_q
    dim3 gBig(HD / 128, MM / 128);            // (16, 32)
    sgemm_bias<128,128,8,8,8><<<gBig, 256>>>(x, W_q, b_q, Qb, MM, HD, EE);

    // K / V projections: [4096,128]
    dim3 gNar(DD / 64, MM / 64);              // (2, 64)
    sgemm_bias<64,64,8,4,4><<<gNar, 256>>>(x, W_k, b_k, Kb, MM, DD, EE);
    sgemm_bias<64,64,8,4,4><<<gNar, 256>>>(x, W_v, b_v, Vb, MM, DD, EE);

    // RoPE in place
    {
        int totQ = MM * HH * (DD / 2);
        rope_kernel<<<(totQ + 255) / 256, 256>>>(Qb, SS, HH, MM);
        int totK = MM * 1 * (DD / 2);
        rope_kernel<<<(totK + 255) / 256, 256>>>(Kb, SS, 1, MM);
    }

    // flash attention
    cudaFuncSetAttribute(flash_attn_kernel,
                         cudaFuncAttributeMaxDynamicSharedMemorySize, FLASH_SMEM);
    flash_attn_kernel<<<dim3(SS / FL_QR, HH, BB), 256, FLASH_SMEM>>>(Qb, Kb, Vb, Ab, SS, HH);

    // output projection: out = A @ W_o + b_o   [4096,2048]
    dim3 gOut(EE / 128, MM / 128);            // (16, 32)
    sgemm_bias<128,128,8,8,8><<<gOut, 256>>>(Ab, W_o, b_o, out, MM, EE, HD);
}